// round 7
// baseline (speedup 1.0000x reference)
#include <cuda_runtime.h>
#include <cstdint>

// out[i,j] = swap_mask[i,j] ? x[i, perm[i,j]] : x[i,j]
// B=16384 rows, F=2048 cols (mask is int32).
// Persistent kernel: 148*8 CTAs, grid-stride over rows, double-buffered SMEM
// row stage (one barrier per row). All global traffic coalesced 16B vectors.

#define N_FEAT   2048
#define THREADS  256
#define PERSIST_CTAS (148 * 8)

__global__ __launch_bounds__(THREADS, 8)
void swap_corruption_kernel(const float* __restrict__ x,
                            const int* __restrict__ mask,
                            const int* __restrict__ perm,
                            float* __restrict__ out,
                            int batch)
{
    __shared__ float srow[2][N_FEAT];

    int pb = 0;
    for (int r = blockIdx.x; r < batch; r += gridDim.x, pb ^= 1) {
        const long long base = (long long)r * N_FEAT;

        const float4* __restrict__ x4 = reinterpret_cast<const float4*>(x + base);
        const int4*   __restrict__ p4 = reinterpret_cast<const int4*>(perm + base);
        const int4*   __restrict__ m4 = reinterpret_cast<const int4*>(mask + base);
        float4*       __restrict__ o4 = reinterpret_cast<float4*>(out + base);

        const int v0 = threadIdx.x;
        const int v1 = THREADS + threadIdx.x;

        // Front-batch all global loads (max MLP)
        const float4 xa = x4[v0];
        const float4 xb = x4[v1];
        const int4   m0 = m4[v0];
        const int4   m1 = m4[v1];
        const int4   p0 = p4[v0];
        const int4   p1 = p4[v1];

        float4* s4 = reinterpret_cast<float4*>(srow[pb]);
        s4[v0] = xa;
        s4[v1] = xb;
        __syncthreads();   // buf ready; also fences prior iteration's reads
                           // of the other buffer before its next overwrite

        const float* sb = srow[pb];
        {
            float4 rr;
            rr.x = m0.x ? sb[p0.x] : xa.x;
            rr.y = m0.y ? sb[p0.y] : xa.y;
            rr.z = m0.z ? sb[p0.z] : xa.z;
            rr.w = m0.w ? sb[p0.w] : xa.w;
            o4[v0] = rr;
        }
        {
            float4 rr;
            rr.x = m1.x ? sb[p1.x] : xb.x;
            rr.y = m1.y ? sb[p1.y] : xb.y;
            rr.z = m1.z ? sb[p1.z] : xb.z;
            rr.w = m1.w ? sb[p1.w] : xb.w;
            o4[v1] = rr;
        }
    }
}

extern "C" void kernel_launch(void* const* d_in, const int* in_sizes, int n_in,
                              void* d_out, int out_size)
{
    const float* x    = (const float*)d_in[0];
    const int*   mask = (const int*)d_in[1];
    const int*   perm = (const int*)d_in[2];
    float*       out  = (float*)d_out;

    const int batch = in_sizes[0] / N_FEAT;      // 16384
    const int grid  = (batch < PERSIST_CTAS) ? batch : PERSIST_CTAS;
    swap_corruption_kernel<<<grid, THREADS>>>(x, mask, perm, out, batch);
}

// round 8
// speedup vs baseline: 1.0466x; 1.0466x over previous
#include <cuda_runtime.h>
#include <cstdint>

// out[i,j] = swap_mask[i,j] ? x[i, perm[i,j]] : x[i,j]
// B=16384 rows, F=2048 cols (mask is int32).
// R3 structure (best: 74.2us kernel, DRAM 87%) + streaming cache hints:
// zero-reuse kernel, so evict-first (.cs) on all loads/stores to let L2
// stream and improve DRAM scheduling.

#define N_FEAT   2048
#define THREADS  256
#define VEC_PER_THREAD (N_FEAT / 4 / THREADS)   // 2 float4 chunks per thread

__global__ __launch_bounds__(THREADS, 8)
void swap_corruption_kernel(const float* __restrict__ x,
                            const int* __restrict__ mask,
                            const int* __restrict__ perm,
                            float* __restrict__ out)
{
    __shared__ float srow[N_FEAT];

    const long long base = (long long)blockIdx.x * N_FEAT;

    const float4* __restrict__ x4 = reinterpret_cast<const float4*>(x + base);
    const int4*   __restrict__ p4 = reinterpret_cast<const int4*>(perm + base);
    const int4*   __restrict__ m4 = reinterpret_cast<const int4*>(mask + base);
    float4*       __restrict__ o4 = reinterpret_cast<float4*>(out + base);

    const int v0 = threadIdx.x;
    const int v1 = THREADS + threadIdx.x;

    // Front-batch all global loads, streaming policy (no reuse anywhere)
    const float4 xa = __ldcs(&x4[v0]);
    const float4 xb = __ldcs(&x4[v1]);
    const int4   p0 = __ldcs(&p4[v0]);
    const int4   p1 = __ldcs(&p4[v1]);
    const int4   m0 = __ldcs(&m4[v0]);
    const int4   m1 = __ldcs(&m4[v1]);

    float4* s4 = reinterpret_cast<float4*>(srow);
    s4[v0] = xa;
    s4[v1] = xb;
    __syncthreads();

    {
        float4 r;
        r.x = m0.x ? srow[p0.x] : xa.x;
        r.y = m0.y ? srow[p0.y] : xa.y;
        r.z = m0.z ? srow[p0.z] : xa.z;
        r.w = m0.w ? srow[p0.w] : xa.w;
        __stcs(&o4[v0], r);
    }
    {
        float4 r;
        r.x = m1.x ? srow[p1.x] : xb.x;
        r.y = m1.y ? srow[p1.y] : xb.y;
        r.z = m1.z ? srow[p1.z] : xb.z;
        r.w = m1.w ? srow[p1.w] : xb.w;
        __stcs(&o4[v1], r);
    }
}

extern "C" void kernel_launch(void* const* d_in, const int* in_sizes, int n_in,
                              void* d_out, int out_size)
{
    const float* x    = (const float*)d_in[0];
    const int*   mask = (const int*)d_in[1];
    const int*   perm = (const int*)d_in[2];
    float*       out  = (float*)d_out;

    const int batch = in_sizes[0] / N_FEAT;      // 16384
    swap_corruption_kernel<<<batch, THREADS>>>(x, mask, perm, out);
}